// round 1
// baseline (speedup 1.0000x reference)
#include <cuda_runtime.h>
#include <cstdint>
#include <cstddef>

#define T_TOK   8192
#define HIDD    2048
#define NQKV    2560
#define DHEAD   256
#define NHEADS  8
#define SEQ     2048
#define NSLOTS  16384

// Scratch (device globals are the sanctioned scratch mechanism)
__device__ float g_qkv[(size_t)T_TOK * NQKV];    // 83.9 MB
__device__ float g_attn[(size_t)T_TOK * HIDD];   // 67.1 MB

// ---------------------------------------------------------------------------
// NT GEMM: C[m][n] = sum_k A[m*K+k] * B[n*K+k]
// 128x128 tile, BK=16, 256 threads, 8x8 micro-tile, double-buffered smem.
// ---------------------------------------------------------------------------
__global__ __launch_bounds__(256, 2)
void gemm_nt_kernel(const float* __restrict__ A, const float* __restrict__ B,
                    float* __restrict__ C, int M, int N, int K)
{
    __shared__ float As[2][16][132];
    __shared__ float Bs[2][16][132];

    const int tid  = threadIdx.x;
    const int warp = tid >> 5, lane = tid & 31;
    const int wm = warp & 3,  wn = warp >> 2;   // 4x2 warps
    const int lm = lane & 3,  ln = lane >> 2;   // 4x8 lanes
    const int row0 = wm * 32 + lm * 8;
    const int col0 = wn * 64 + ln * 8;

    const int lrow = tid >> 2;          // 0..63
    const int lk4  = (tid & 3) << 2;    // 0,4,8,12

    const float* Ap = A + (size_t)(blockIdx.y * 128 + lrow) * K + lk4;
    const float* Bp = B + (size_t)(blockIdx.x * 128 + lrow) * K + lk4;

    float acc[8][8];
    #pragma unroll
    for (int i = 0; i < 8; i++)
        #pragma unroll
        for (int j = 0; j < 8; j++) acc[i][j] = 0.f;

    float4 ar[2], br[2];
    ar[0] = *(const float4*)(Ap);
    ar[1] = *(const float4*)(Ap + (size_t)64 * K);
    br[0] = *(const float4*)(Bp);
    br[1] = *(const float4*)(Bp + (size_t)64 * K);

#define GEMM_STS(BUFI) do {                                                  \
    _Pragma("unroll")                                                        \
    for (int i = 0; i < 2; i++) {                                            \
        As[BUFI][lk4+0][lrow+64*i] = ((float*)&ar[i])[0];                    \
        As[BUFI][lk4+1][lrow+64*i] = ((float*)&ar[i])[1];                    \
        As[BUFI][lk4+2][lrow+64*i] = ((float*)&ar[i])[2];                    \
        As[BUFI][lk4+3][lrow+64*i] = ((float*)&ar[i])[3];                    \
        Bs[BUFI][lk4+0][lrow+64*i] = ((float*)&br[i])[0];                    \
        Bs[BUFI][lk4+1][lrow+64*i] = ((float*)&br[i])[1];                    \
        Bs[BUFI][lk4+2][lrow+64*i] = ((float*)&br[i])[2];                    \
        Bs[BUFI][lk4+3][lrow+64*i] = ((float*)&br[i])[3];                    \
    } } while (0)

    GEMM_STS(0);
    __syncthreads();

    const int nt = K >> 4;
    for (int t = 0; t < nt; t++) {
        const int buf = t & 1;
        if (t + 1 < nt) {
            const float* Ap2 = Ap + (t + 1) * 16;
            const float* Bp2 = Bp + (t + 1) * 16;
            ar[0] = *(const float4*)(Ap2);
            ar[1] = *(const float4*)(Ap2 + (size_t)64 * K);
            br[0] = *(const float4*)(Bp2);
            br[1] = *(const float4*)(Bp2 + (size_t)64 * K);
        }
        #pragma unroll
        for (int kk = 0; kk < 16; kk++) {
            float4 a0 = *(const float4*)&As[buf][kk][row0];
            float4 a1 = *(const float4*)&As[buf][kk][row0 + 4];
            float4 b0 = *(const float4*)&Bs[buf][kk][col0];
            float4 b1 = *(const float4*)&Bs[buf][kk][col0 + 4];
            float av[8] = {a0.x, a0.y, a0.z, a0.w, a1.x, a1.y, a1.z, a1.w};
            float bv[8] = {b0.x, b0.y, b0.z, b0.w, b1.x, b1.y, b1.z, b1.w};
            #pragma unroll
            for (int i = 0; i < 8; i++)
                #pragma unroll
                for (int j = 0; j < 8; j++)
                    acc[i][j] += av[i] * bv[j];
        }
        if (t + 1 < nt) {
            __syncthreads();
            GEMM_STS(buf ^ 1);
            __syncthreads();
        }
    }

    float* Cp = C + (size_t)(blockIdx.y * 128 + row0) * N + blockIdx.x * 128 + col0;
    #pragma unroll
    for (int i = 0; i < 8; i++) {
        float4 c0 = make_float4(acc[i][0], acc[i][1], acc[i][2], acc[i][3]);
        float4 c1 = make_float4(acc[i][4], acc[i][5], acc[i][6], acc[i][7]);
        *(float4*)(Cp + (size_t)i * N)     = c0;
        *(float4*)(Cp + (size_t)i * N + 4) = c1;
    }
#undef GEMM_STS
}

// ---------------------------------------------------------------------------
// RoPE (in place on g_qkv) + KV cache scatter.
// One block per token, 128 threads (one per rotation pair).
// ---------------------------------------------------------------------------
__global__ void rope_kernel(float* __restrict__ qkv,
                            const float* __restrict__ cosp,
                            const float* __restrict__ sinp,
                            const int* __restrict__ slots,
                            float* __restrict__ kc_out,
                            float* __restrict__ vc_out)
{
    const int t = blockIdx.x;
    const int d = threadIdx.x;   // 0..127
    const float c = cosp[t * 128 + d];
    const float s = sinp[t * 128 + d];
    float* row = qkv + (size_t)t * NQKV;

    #pragma unroll
    for (int hh = 0; hh < NHEADS + 1; hh++) {   // 8 q heads + 1 k head
        float* x = row + hh * DHEAD;
        float x1 = x[d], x2 = x[d + 128];
        x[d]       = x1 * c - x2 * s;
        x[d + 128] = x2 * c + x1 * s;
    }

    const int slot = slots[t];
    const float* krow = row + NHEADS * DHEAD;        // rope'd k
    const float* vrow = krow + DHEAD;                // raw v
    kc_out[(size_t)slot * DHEAD + d]       = krow[d];
    kc_out[(size_t)slot * DHEAD + 128 + d] = krow[d + 128];
    vc_out[(size_t)slot * DHEAD + d]       = vrow[d];
    vc_out[(size_t)slot * DHEAD + 128 + d] = vrow[d + 128];
}

// ---------------------------------------------------------------------------
// Flash attention (fp32, causal, MQA KV=1).
// CTA: 64 queries x 1 head. 256 threads. Tiles of 64 keys.
// smem: Qs[256][68] (transposed, pre-scaled), Kst[256][68] (transposed),
//       Vs[64][260], Ps[64][68] (P transposed), m/l/f rows.
// ---------------------------------------------------------------------------
__device__ __forceinline__ void load_tile_T64(float* __restrict__ dst,
                                              const float* __restrict__ src,
                                              int tid, float scl)
{
    // 64 rows x 256 cols (row stride NQKV) -> dst[d][row], stride 68, scaled.
    #pragma unroll
    for (int rep = 0; rep < 4; rep++) {
        int mu = rep * 256 + tid;
        int d4 = mu & 63, c4 = mu >> 6;     // c4: 0..15
        float4 v0 = *(const float4*)(src + (size_t)(c4 * 4 + 0) * NQKV + d4 * 4);
        float4 v1 = *(const float4*)(src + (size_t)(c4 * 4 + 1) * NQKV + d4 * 4);
        float4 v2 = *(const float4*)(src + (size_t)(c4 * 4 + 2) * NQKV + d4 * 4);
        float4 v3 = *(const float4*)(src + (size_t)(c4 * 4 + 3) * NQKV + d4 * 4);
        float* dp = dst + (size_t)(4 * d4) * 68 + c4 * 4;
        *(float4*)(dp)       = make_float4(v0.x * scl, v1.x * scl, v2.x * scl, v3.x * scl);
        *(float4*)(dp +  68) = make_float4(v0.y * scl, v1.y * scl, v2.y * scl, v3.y * scl);
        *(float4*)(dp + 136) = make_float4(v0.z * scl, v1.z * scl, v2.z * scl, v3.z * scl);
        *(float4*)(dp + 204) = make_float4(v0.w * scl, v1.w * scl, v2.w * scl, v3.w * scl);
    }
}

__global__ __launch_bounds__(256, 1)
void attn_kernel(const float* __restrict__ qkv, float* __restrict__ attn)
{
    extern __shared__ float sm[];
    float* Qs  = sm;            // 256*68 = 17408
    float* Kst = sm + 17408;    // 256*68
    float* Vs  = sm + 34816;    // 64*260 = 16640
    float* Ps  = sm + 51456;    // 64*68  = 4352
    float* Ms  = sm + 55808;    // 64
    float* Ls  = sm + 55872;    // 64
    float* Fs  = sm + 55936;    // 64   -> total 56000 floats = 224000 B

    const int tid = threadIdx.x;
    const int qb = blockIdx.x, h = blockIdx.y, b = blockIdx.z;

    const float* Qsrc = qkv + (size_t)(b * SEQ + qb * 64) * NQKV + h * DHEAD;
    load_tile_T64(Qs, Qsrc, tid, 0.0625f);   // fold D^-1/2 into Q
    if (tid < 64) { Ms[tid] = -1e30f; Ls[tid] = 0.f; }

    const int ty  = tid >> 4, tx  = tid & 15;   // score stage: 4q x 4k
    const int ty2 = tid >> 5, tx2 = tid & 31;   // PV stage: 8q x (4+4)d

    float O[8][8];
    #pragma unroll
    for (int i = 0; i < 8; i++)
        #pragma unroll
        for (int j = 0; j < 8; j++) O[i][j] = 0.f;

    __syncthreads();

    for (int kt = 0; kt <= qb; kt++) {
        const float* Ksrc = qkv + (size_t)(b * SEQ + kt * 64) * NQKV + NHEADS * DHEAD;
        load_tile_T64(Kst, Ksrc, tid, 1.0f);
        // V tile: row-major [64][260]
        #pragma unroll
        for (int rep = 0; rep < 16; rep++) {
            int idx = rep * 256 + tid;
            int c = idx >> 6, d4 = idx & 63;
            *(float4*)(Vs + (size_t)c * 260 + d4 * 4) =
                *(const float4*)(Ksrc + DHEAD + (size_t)c * NQKV + d4 * 4);
        }
        __syncthreads();

        // ---- scores: s[i][j] = sum_d Q[4ty+i][d] * K[4tx+j][d]
        float s[4][4];
        #pragma unroll
        for (int i = 0; i < 4; i++)
            #pragma unroll
            for (int j = 0; j < 4; j++) s[i][j] = 0.f;

        const float* qp = Qs + ty * 4;
        const float* kp = Kst + tx * 4;
        #pragma unroll 8
        for (int d = 0; d < 256; d++) {
            float4 qv = *(const float4*)(qp + (size_t)d * 68);
            float4 kv = *(const float4*)(kp + (size_t)d * 68);
            float qa[4] = {qv.x, qv.y, qv.z, qv.w};
            float ka[4] = {kv.x, kv.y, kv.z, kv.w};
            #pragma unroll
            for (int i = 0; i < 4; i++)
                #pragma unroll
                for (int j = 0; j < 4; j++)
                    s[i][j] += qa[i] * ka[j];
        }

        if (kt == qb) {  // diagonal tile: causal mask
            #pragma unroll
            for (int i = 0; i < 4; i++)
                #pragma unroll
                for (int j = 0; j < 4; j++)
                    if (tx * 4 + j > ty * 4 + i) s[i][j] = -1e30f;
        }

        // ---- online softmax per row (16-lane tx-group reductions)
        #pragma unroll
        for (int i = 0; i < 4; i++) {
            const int r = ty * 4 + i;
            float rm = fmaxf(fmaxf(s[i][0], s[i][1]), fmaxf(s[i][2], s[i][3]));
            rm = fmaxf(rm, __shfl_xor_sync(0xffffffffu, rm, 8));
            rm = fmaxf(rm, __shfl_xor_sync(0xffffffffu, rm, 4));
            rm = fmaxf(rm, __shfl_xor_sync(0xffffffffu, rm, 2));
            rm = fmaxf(rm, __shfl_xor_sync(0xffffffffu, rm, 1));
            float mo = Ms[r];
            float mn = fmaxf(mo, rm);
            float p0 = __expf(s[i][0] - mn);
            float p1 = __expf(s[i][1] - mn);
            float p2 = __expf(s[i][2] - mn);
            float p3 = __expf(s[i][3] - mn);
            float ls = p0 + p1 + p2 + p3;
            ls += __shfl_xor_sync(0xffffffffu, ls, 8);
            ls += __shfl_xor_sync(0xffffffffu, ls, 4);
            ls += __shfl_xor_sync(0xffffffffu, ls, 2);
            ls += __shfl_xor_sync(0xffffffffu, ls, 1);
            Ps[(size_t)(tx * 4 + 0) * 68 + r] = p0;
            Ps[(size_t)(tx * 4 + 1) * 68 + r] = p1;
            Ps[(size_t)(tx * 4 + 2) * 68 + r] = p2;
            Ps[(size_t)(tx * 4 + 3) * 68 + r] = p3;
            if (tx == 0) {
                Ms[r] = mn;
                float f = __expf(mo - mn);
                Fs[r] = f;
                Ls[r] = Ls[r] * f + ls;
            }
        }
        __syncthreads();

        // ---- rescale O and accumulate P*V
        {
            float f[8];
            #pragma unroll
            for (int i = 0; i < 8; i++) f[i] = Fs[ty2 * 8 + i];
            #pragma unroll
            for (int i = 0; i < 8; i++)
                #pragma unroll
                for (int j = 0; j < 8; j++) O[i][j] *= f[i];
        }
        const float* pp = Ps + ty2 * 8;
        const float* vp = Vs + tx2 * 4;
        #pragma unroll 4
        for (int k = 0; k < 64; k++) {
            float4 pa = *(const float4*)(pp + (size_t)k * 68);
            float4 pb = *(const float4*)(pp + (size_t)k * 68 + 4);
            float4 va = *(const float4*)(vp + (size_t)k * 260);
            float4 vb = *(const float4*)(vp + (size_t)k * 260 + 128);
            float pr[8] = {pa.x, pa.y, pa.z, pa.w, pb.x, pb.y, pb.z, pb.w};
            float vr0[4] = {va.x, va.y, va.z, va.w};
            float vr1[4] = {vb.x, vb.y, vb.z, vb.w};
            #pragma unroll
            for (int i = 0; i < 8; i++) {
                #pragma unroll
                for (int j = 0; j < 4; j++) O[i][j]     += pr[i] * vr0[j];
                #pragma unroll
                for (int j = 0; j < 4; j++) O[i][4 + j] += pr[i] * vr1[j];
            }
        }
        __syncthreads();
    }

    // ---- epilogue: normalize and store
    float* obase = attn + (size_t)(b * SEQ + qb * 64 + ty2 * 8) * HIDD + h * DHEAD + tx2 * 4;
    #pragma unroll
    for (int i = 0; i < 8; i++) {
        float inv = 1.0f / Ls[ty2 * 8 + i];
        float4 o0 = make_float4(O[i][0] * inv, O[i][1] * inv, O[i][2] * inv, O[i][3] * inv);
        float4 o1 = make_float4(O[i][4] * inv, O[i][5] * inv, O[i][6] * inv, O[i][7] * inv);
        *(float4*)(obase + (size_t)i * HIDD)       = o0;
        *(float4*)(obase + (size_t)i * HIDD + 128) = o1;
    }
}

// ---------------------------------------------------------------------------
// Launch
// ---------------------------------------------------------------------------
extern "C" void kernel_launch(void* const* d_in, const int* in_sizes, int n_in,
                              void* d_out, int out_size)
{
    (void)in_sizes; (void)n_in; (void)out_size;
    const float* hidden = (const float*)d_in[0];
    const float* cosp   = (const float*)d_in[1];
    const float* sinp   = (const float*)d_in[2];
    const int*   slots  = (const int*)d_in[3];
    const float* kc_in  = (const float*)d_in[4];
    const float* vc_in  = (const float*)d_in[5];
    const float* wqkv   = (const float*)d_in[6];
    const float* wo     = (const float*)d_in[7];

    float* out    = (float*)d_out;
    float* kc_out = out + (size_t)T_TOK * HIDD;          // after attention output
    float* vc_out = kc_out + (size_t)NSLOTS * DHEAD;

    float *qkv = nullptr, *attn = nullptr;
    cudaGetSymbolAddress((void**)&qkv,  g_qkv);
    cudaGetSymbolAddress((void**)&attn, g_attn);

    // Cache passthrough (untouched slots keep input values)
    cudaMemcpyAsync(kc_out, kc_in, (size_t)NSLOTS * DHEAD * sizeof(float),
                    cudaMemcpyDeviceToDevice);
    cudaMemcpyAsync(vc_out, vc_in, (size_t)NSLOTS * DHEAD * sizeof(float),
                    cudaMemcpyDeviceToDevice);

    // 1) QKV projection: [8192,2048] x [2560,2048]^T
    gemm_nt_kernel<<<dim3(NQKV / 128, T_TOK / 128), 256>>>(
        hidden, wqkv, qkv, T_TOK, NQKV, HIDD);

    // 2) RoPE (q,k in place) + cache scatter
    rope_kernel<<<T_TOK, 128>>>(qkv, cosp, sinp, slots, kc_out, vc_out);

    // 3) Causal flash attention
    cudaFuncSetAttribute(attn_kernel,
                         cudaFuncAttributeMaxDynamicSharedMemorySize, 224000);
    attn_kernel<<<dim3(SEQ / 64, NHEADS, 4), 256, 224000>>>(qkv, attn);

    // 4) Output projection: [8192,2048] x [2048,2048]^T
    gemm_nt_kernel<<<dim3(HIDD / 128, T_TOK / 128), 256>>>(
        attn, wo, out, T_TOK, HIDD, HIDD);
}

// round 6
// speedup vs baseline: 1.3295x; 1.3295x over previous
#include <cuda_runtime.h>
#include <cuda_bf16.h>
#include <cstdint>
#include <cstddef>

#define T_TOK   8192
#define HIDD    2048
#define NQKV    2560
#define DHEAD   256
#define NHEADS  8
#define SEQ     2048
#define NSLOTS  16384
#define KP      6144        // packed K' = 3*2048

// ---------------- scratch (device globals = sanctioned scratch) ----------------
__device__ float g_qkv[(size_t)T_TOK * NQKV];
__device__ float g_attn[(size_t)T_TOK * HIDD];
__device__ __nv_bfloat16 g_packA[(size_t)T_TOK * KP];
__device__ __nv_bfloat16 g_packB[(size_t)NQKV * KP];

__device__ __forceinline__ uint32_t smem_u32(const void* p) {
    uint32_t a;
    asm("{ .reg .u64 t; cvta.to.shared.u64 t, %1; cvt.u32.u64 %0, t; }" : "=r"(a) : "l"(p));
    return a;
}

#define SWZ(o) ((o) ^ (((o) >> 3) & 0x70))

#define CP_ASYNC16(dst, src) \
    asm volatile("cp.async.cg.shared.global [%0], [%1], 16;" :: "r"(dst), "l"(src))
#define CP_COMMIT() asm volatile("cp.async.commit_group;" ::: "memory")
#define CP_WAIT(n)  asm volatile("cp.async.wait_group %0;" :: "n"(n) : "memory")

__device__ __forceinline__ void ldsm_x4(uint32_t* r, uint32_t addr) {
    asm volatile("ldmatrix.sync.aligned.m8n8.x4.shared.b16 {%0,%1,%2,%3}, [%4];"
        : "=r"(r[0]), "=r"(r[1]), "=r"(r[2]), "=r"(r[3]) : "r"(addr));
}

__device__ __forceinline__ void mma16816(float* d, const uint32_t* a, const uint32_t* b) {
    asm volatile(
        "mma.sync.aligned.m16n8k16.row.col.f32.bf16.bf16.f32 "
        "{%0,%1,%2,%3}, {%4,%5,%6,%7}, {%8,%9}, {%0,%1,%2,%3};"
        : "+f"(d[0]), "+f"(d[1]), "+f"(d[2]), "+f"(d[3])
        : "r"(a[0]), "r"(a[1]), "r"(a[2]), "r"(a[3]), "r"(b[0]), "r"(b[1]));
}

// ---------------------------------------------------------------------------
// Pack fp32 -> bf16x3 K-concat. mode 0 (A-side): [hi | lo | hi]
//                               mode 1 (B-side): [hi | hi | lo]
// ---------------------------------------------------------------------------
__global__ void pack_split_kernel(const float* __restrict__ src,
                                  __nv_bfloat16* __restrict__ dst,
                                  int mode, long total)
{
    long idx = (long)blockIdx.x * blockDim.x + threadIdx.x;
    if (idx >= total) return;
    int k = (int)(idx & 2047);
    long r = idx >> 11;
    float x = src[idx];
    __nv_bfloat16 hi = __float2bfloat16_rn(x);
    __nv_bfloat16 lo = __float2bfloat16_rn(x - __bfloat162float(hi));
    __nv_bfloat16* base = dst + r * KP + k;
    if (mode == 0) { base[0] = hi; base[2048] = lo; base[4096] = hi; }
    else           { base[0] = hi; base[2048] = hi; base[4096] = lo; }
}

// ---------------------------------------------------------------------------
// bf16 NT GEMM via mma.sync (HMMA): C[m][n] = sum_k A'[m][k]*B'[n][k], K'=6144
// 128x128 CTA tile, BK=64 bf16 (128B rows, SW128 swizzle), 4-stage cp.async
// pipeline, 8 warps (4x2), warp tile 32x64, m16n8k16 fragments.
// ---------------------------------------------------------------------------
#define STAGES  4
#define TILEB   16384       // 128 rows x 128 bytes
#define STAGEB  (2 * TILEB)
#define NCH     (KP / 64)   // 96

__global__ __launch_bounds__(256, 1)
void gemm_mma_kernel(const __nv_bfloat16* __restrict__ A,
                     const __nv_bfloat16* __restrict__ B,
                     float* __restrict__ C, int ldc)
{
    extern __shared__ char smc[];
    const uint32_t sbase = smem_u32(smc);
    const int tid  = threadIdx.x;
    const int warp = tid >> 5, lane = tid & 31;
    const int wm = (warp & 3) * 32;     // warp m-offset in tile
    const int wn = (warp >> 2) * 64;    // warp n-offset in tile
    const int mBase = blockIdx.y * 128;
    const int nBase = blockIdx.x * 128;

    // cp.async mapping: thread -> (row, 4 consecutive 16B chunks)
    const int lrow = tid >> 1;          // 0..127
    const int lc0  = (tid & 1) * 4;     // 0 or 4

    const char* Ag = (const char*)A + (size_t)(mBase + lrow) * (KP * 2) + lc0 * 16;
    const char* Bg = (const char*)B + (size_t)(nBase + lrow) * (KP * 2) + lc0 * 16;
    const uint32_t swbase = SWZ((uint32_t)(lrow * 128 + lc0 * 16));
    // 4 consecutive 16B chunks starting at lc0: swizzle XORs bits [6:4] with
    // row bits, chunk index bits are [6:4]; consecutive chunks map to
    // consecutive XORed positions -> compute each.

#define LOAD_STAGE(stage, chunk) do {                                        \
    uint32_t _sa = sbase + (stage) * STAGEB;                                 \
    uint32_t _sb = _sa + TILEB;                                              \
    size_t _go = (size_t)(chunk) * 128;                                      \
    _Pragma("unroll")                                                        \
    for (int _c = 0; _c < 4; _c++) {                                         \
        uint32_t _off = lrow * 128 + (lc0 + _c) * 16;                        \
        uint32_t _sw  = SWZ(_off);                                           \
        CP_ASYNC16(_sa + _sw, Ag + _go + _c * 16);                           \
        CP_ASYNC16(_sb + _sw, Bg + _go + _c * 16);                           \
    } } while (0)

    (void)swbase;

    float acc[2][8][4];
    #pragma unroll
    for (int i = 0; i < 2; i++)
        #pragma unroll
        for (int j = 0; j < 8; j++)
            #pragma unroll
            for (int q = 0; q < 4; q++) acc[i][j][q] = 0.f;

    // prologue: stages 0..2 <- chunks 0..2
    #pragma unroll
    for (int s = 0; s < STAGES - 1; s++) { LOAD_STAGE(s, s); CP_COMMIT(); }

    // precomputed ldmatrix offsets (unswizzled parts)
    const uint32_t arow = wm + (lane & 15);
    const uint32_t acol16 = (lane >> 4) * 16;
    const uint32_t brow_lo = wn + (lane & 7) + ((lane >> 4) * 8);
    const uint32_t bcol16 = ((lane >> 3) & 1) * 16;

    for (int it = 0; it < NCH; it++) {
        CP_WAIT(2);
        __syncthreads();
        const uint32_t sa = sbase + (it & 3) * STAGEB;
        const uint32_t sb = sa + TILEB;

        #pragma unroll
        for (int ks = 0; ks < 4; ks++) {
            uint32_t a0[4], a1[4];
            uint32_t ao = arow * 128 + ks * 32 + acol16;
            ldsm_x4(a0, sa + SWZ(ao));
            ao += 16 * 128;
            ldsm_x4(a1, sa + SWZ(ao));
            uint32_t bf[4][4];
            #pragma unroll
            for (int nt = 0; nt < 4; nt++) {
                uint32_t bo = (brow_lo + nt * 16) * 128 + ks * 32 + bcol16;
                ldsm_x4(bf[nt], sb + SWZ(bo));
            }
            #pragma unroll
            for (int nt = 0; nt < 4; nt++) {
                mma16816(acc[0][nt * 2],     a0, &bf[nt][0]);
                mma16816(acc[0][nt * 2 + 1], a0, &bf[nt][2]);
                mma16816(acc[1][nt * 2],     a1, &bf[nt][0]);
                mma16816(acc[1][nt * 2 + 1], a1, &bf[nt][2]);
            }
        }

        int nx = it + STAGES - 1;
        if (nx < NCH) LOAD_STAGE(nx & 3, nx);
        CP_COMMIT();
    }
#undef LOAD_STAGE

    // epilogue: d-frag mapping: row = lane/4 (+8 for regs 2,3), col = (lane%4)*2
    const int r0 = mBase + wm + (lane >> 2);
    const int c0 = nBase + wn + (lane & 3) * 2;
    #pragma unroll
    for (int mt = 0; mt < 2; mt++) {
        #pragma unroll
        for (int nt = 0; nt < 8; nt++) {
            const int r = r0 + mt * 16;
            const int c = c0 + nt * 8;
            *(float2*)&C[(size_t)r * ldc + c]       = make_float2(acc[mt][nt][0], acc[mt][nt][1]);
            *(float2*)&C[(size_t)(r + 8) * ldc + c] = make_float2(acc[mt][nt][2], acc[mt][nt][3]);
        }
    }
}

// ---------------------------------------------------------------------------
// RoPE (in place on g_qkv) + KV cache scatter.
// ---------------------------------------------------------------------------
__global__ void rope_kernel(float* __restrict__ qkv,
                            const float* __restrict__ cosp,
                            const float* __restrict__ sinp,
                            const int* __restrict__ slots,
                            float* __restrict__ kc_out,
                            float* __restrict__ vc_out)
{
    const int t = blockIdx.x;
    const int d = threadIdx.x;
    const float c = cosp[t * 128 + d];
    const float s = sinp[t * 128 + d];
    float* row = qkv + (size_t)t * NQKV;

    #pragma unroll
    for (int hh = 0; hh < NHEADS + 1; hh++) {
        float* x = row + hh * DHEAD;
        float x1 = x[d], x2 = x[d + 128];
        x[d]       = x1 * c - x2 * s;
        x[d + 128] = x2 * c + x1 * s;
    }

    const int slot = slots[t];
    const float* krow = row + NHEADS * DHEAD;
    const float* vrow = krow + DHEAD;
    kc_out[(size_t)slot * DHEAD + d]       = krow[d];
    kc_out[(size_t)slot * DHEAD + 128 + d] = krow[d + 128];
    vc_out[(size_t)slot * DHEAD + d]       = vrow[d];
    vc_out[(size_t)slot * DHEAD + 128 + d] = vrow[d + 128];
}

// ---------------------------------------------------------------------------
// Flash attention fp32 (unchanged, known-good).
// ---------------------------------------------------------------------------
__device__ __forceinline__ void load_tile_T64(float* __restrict__ dst,
                                              const float* __restrict__ src,
                                              int tid, float scl)
{
    #pragma unroll
    for (int rep = 0; rep < 4; rep++) {
        int mu = rep * 256 + tid;
        int d4 = mu & 63, c4 = mu >> 6;
        float4 v0 = *(const float4*)(src + (size_t)(c4 * 4 + 0) * NQKV + d4 * 4);
        float4 v1 = *(const float4*)(src + (size_t)(c4 * 4 + 1) * NQKV + d4 * 4);
        float4 v2 = *(const float4*)(src + (size_t)(c4 * 4 + 2) * NQKV + d4 * 4);
        float4 v3 = *(const float4*)(src + (size_t)(c4 * 4 + 3) * NQKV + d4 * 4);
        float* dp = dst + (size_t)(4 * d4) * 68 + c4 * 4;
        *(float4*)(dp)       = make_float4(v0.x * scl, v1.x * scl, v2.x * scl, v3.x * scl);
        *(float4*)(dp +  68) = make_float4(v0.y * scl, v1.y * scl, v2.y * scl, v3.y * scl);
        *(float4*)(dp + 136) = make_float4(v0.z * scl, v1.z * scl, v2.z * scl, v3.z * scl);
        *(float4*)(dp + 204) = make_float4(v0.w * scl, v1.w * scl, v2.w * scl, v3.w * scl);
    }
}

__global__ __launch_bounds__(256, 1)
void attn_kernel(const float* __restrict__ qkv, float* __restrict__ attn)
{
    extern __shared__ float sm[];
    float* Qs  = sm;
    float* Kst = sm + 17408;
    float* Vs  = sm + 34816;
    float* Ps  = sm + 51456;
    float* Ms  = sm + 55808;
    float* Ls  = sm + 55872;
    float* Fs  = sm + 55936;

    const int tid = threadIdx.x;
    const int qb = blockIdx.x, h = blockIdx.y, b = blockIdx.z;

    const float* Qsrc = qkv + (size_t)(b * SEQ + qb * 64) * NQKV + h * DHEAD;
    load_tile_T64(Qs, Qsrc, tid, 0.0625f);
    if (tid < 64) { Ms[tid] = -1e30f; Ls[tid] = 0.f; }

    const int ty  = tid >> 4, tx  = tid & 15;
    const int ty2 = tid >> 5, tx2 = tid & 31;

    float O[8][8];
    #pragma unroll
    for (int i = 0; i < 8; i++)
        #pragma unroll
        for (int j = 0; j < 8; j++) O[i][j] = 0.f;

    __syncthreads();

    for (int kt = 0; kt <= qb; kt++) {
        const float* Ksrc = qkv + (size_t)(b * SEQ + kt * 64) * NQKV + NHEADS * DHEAD;
        load_tile_T64(Kst, Ksrc, tid, 1.0f);
        #pragma unroll
        for (int rep = 0; rep < 16; rep++) {
            int idx = rep * 256 + tid;
            int c = idx >> 6, d4 = idx & 63;
            *(float4*)(Vs + (size_t)c * 260 + d4 * 4) =
                *(const float4*)(Ksrc + DHEAD + (size_t)c * NQKV + d4 * 4);
        }
        __syncthreads();

        float s[4][4];
        #pragma unroll
        for (int i = 0; i < 4; i++)
            #pragma unroll
            for (int j = 0; j < 4; j++) s[i][j] = 0.f;

        const float* qp = Qs + ty * 4;
        const float* kp = Kst + tx * 4;
        #pragma unroll 8
        for (int d = 0; d < 256; d++) {
            float4 qv = *(const float4*)(qp + (size_t)d * 68);
            float4 kv = *(const float4*)(kp + (size_t)d * 68);
            float qa[4] = {qv.x, qv.y, qv.z, qv.w};
            float ka[4] = {kv.x, kv.y, kv.z, kv.w};
            #pragma unroll
            for (int i = 0; i < 4; i++)
                #pragma unroll
                for (int j = 0; j < 4; j++)
                    s[i][j] += qa[i] * ka[j];
        }

        if (kt == qb) {
            #pragma unroll
            for (int i = 0; i < 4; i++)
                #pragma unroll
                for (int j = 0; j < 4; j++)
                    if (tx * 4 + j > ty * 4 + i) s[i][j] = -1e30f;
        }

        #pragma unroll
        for (int i = 0; i < 4; i++) {
            const int r = ty * 4 + i;
            float rm = fmaxf(fmaxf(s[i][0], s[i][1]), fmaxf(s[i][2], s[i][3]));
            rm = fmaxf(rm, __shfl_xor_sync(0xffffffffu, rm, 8));
            rm = fmaxf(rm, __shfl_xor_sync(0xffffffffu, rm, 4));
            rm = fmaxf(rm, __shfl_xor_sync(0xffffffffu, rm, 2));
            rm = fmaxf(rm, __shfl_xor_sync(0xffffffffu, rm, 1));
            float mo = Ms[r];
            float mn = fmaxf(mo, rm);
            float p0 = __expf(s[i][0] - mn);
            float p1 = __expf(s[i][1] - mn);
            float p2 = __expf(s[i][2] - mn);
            float p3 = __expf(s[i][3] - mn);
            float ls = p0 + p1 + p2 + p3;
            ls += __shfl_xor_sync(0xffffffffu, ls, 8);
            ls += __shfl_xor_sync(0xffffffffu, ls, 4);
            ls += __shfl_xor_sync(0xffffffffu, ls, 2);
            ls += __shfl_xor_sync(0xffffffffu, ls, 1);
            Ps[(size_t)(tx * 4 + 0) * 68 + r] = p0;
            Ps[(size_t)(tx * 4 + 1) * 68 + r] = p1;
            Ps[(size_t)(tx * 4 + 2) * 68 + r] = p2;
            Ps[(size_t)(tx * 4 + 3) * 68 + r] = p3;
            if (tx == 0) {
                Ms[r] = mn;
                float f = __expf(mo - mn);
                Fs[r] = f;
                Ls[r] = Ls[r] * f + ls;
            }
        }
        __syncthreads();

        {
            float f[8];
            #pragma unroll
            for (int i = 0; i < 8; i++) f[i] = Fs[ty2 * 8 + i];
            #pragma unroll
            for (int i = 0; i < 8; i++)
                #pragma unroll
                for (int j = 0; j < 8; j++) O[i][j] *= f[i];
        }
        const float* pp = Ps + ty2 * 8;
        const float* vp = Vs + tx2 * 4;
        #pragma unroll 4
        for (int k = 0; k < 64; k++) {
            float4 pa = *(const float4*)(pp + (size_t)k * 68);
            float4 pb = *(const float4*)(pp + (size_t)k * 68 + 4);
            float4 va = *(const float4*)(vp + (size_t)k * 260);
            float4 vb = *(const float4*)(vp + (size_t)k * 260 + 128);
            float pr[8] = {pa.x, pa.y, pa.z, pa.w, pb.x, pb.y, pb.z, pb.w};
            float vr0[4] = {va.x, va.y, va.z, va.w};
            float vr1[4] = {vb.x, vb.y, vb.z, vb.w};
            #pragma unroll
            for (int i = 0; i < 8; i++) {
                #pragma unroll
                for (int j = 0; j < 4; j++) O[i][j]     += pr[i] * vr0[j];
                #pragma unroll
                for (int j = 0; j < 4; j++) O[i][4 + j] += pr[i] * vr1[j];
            }
        }
        __syncthreads();
    }

    float* obase = attn + (size_t)(b * SEQ + qb * 64 + ty2 * 8) * HIDD + h * DHEAD + tx2 * 4;
    #pragma unroll
    for (int i = 0; i < 8; i++) {
        float inv = 1.0f / Ls[ty2 * 8 + i];
        float4 o0 = make_float4(O[i][0] * inv, O[i][1] * inv, O[i][2] * inv, O[i][3] * inv);
        float4 o1 = make_float4(O[i][4] * inv, O[i][5] * inv, O[i][6] * inv, O[i][7] * inv);
        *(float4*)(obase + (size_t)i * HIDD)       = o0;
        *(float4*)(obase + (size_t)i * HIDD + 128) = o1;
    }
}

// ---------------------------------------------------------------------------
// Launch
// ---------------------------------------------------------------------------
extern "C" void kernel_launch(void* const* d_in, const int* in_sizes, int n_in,
                              void* d_out, int out_size)
{
    (void)in_sizes; (void)n_in; (void)out_size;
    const float* hidden = (const float*)d_in[0];
    const float* cosp   = (const float*)d_in[1];
    const float* sinp   = (const float*)d_in[2];
    const int*   slots  = (const int*)d_in[3];
    const float* kc_in  = (const float*)d_in[4];
    const float* vc_in  = (const float*)d_in[5];
    const float* wqkv   = (const float*)d_in[6];
    const float* wo     = (const float*)d_in[7];

    float* out    = (float*)d_out;
    float* kc_out = out + (size_t)T_TOK * HIDD;
    float* vc_out = kc_out + (size_t)NSLOTS * DHEAD;

    float *qkv = nullptr, *attn = nullptr;
    __nv_bfloat16 *pA = nullptr, *pB = nullptr;
    cudaGetSymbolAddress((void**)&qkv,  g_qkv);
    cudaGetSymbolAddress((void**)&attn, g_attn);
    cudaGetSymbolAddress((void**)&pA,   g_packA);
    cudaGetSymbolAddress((void**)&pB,   g_packB);

    const int gemm_smem = STAGES * STAGEB;   // 131072
    cudaFuncSetAttribute(gemm_mma_kernel,
                         cudaFuncAttributeMaxDynamicSharedMemorySize, gemm_smem);
    cudaFuncSetAttribute(attn_kernel,
                         cudaFuncAttributeMaxDynamicSharedMemorySize, 224000);

    cudaMemcpyAsync(kc_out, kc_in, (size_t)NSLOTS * DHEAD * sizeof(float),
                    cudaMemcpyDeviceToDevice);
    cudaMemcpyAsync(vc_out, vc_in, (size_t)NSLOTS * DHEAD * sizeof(float),
                    cudaMemcpyDeviceToDevice);

    // 1) QKV projection (bf16x3 via mma.sync)
    {
        long tA = (long)T_TOK * HIDD;
        long tB = (long)NQKV * HIDD;
        pack_split_kernel<<<(unsigned)((tA + 255) / 256), 256>>>(hidden, pA, 0, tA);
        pack_split_kernel<<<(unsigned)((tB + 255) / 256), 256>>>(wqkv,   pB, 1, tB);
        gemm_mma_kernel<<<dim3(NQKV / 128, T_TOK / 128), 256, gemm_smem>>>(pA, pB, qkv, NQKV);
    }

    // 2) RoPE + cache scatter
    rope_kernel<<<T_TOK, 128>>>(qkv, cosp, sinp, slots, kc_out, vc_out);

    // 3) Causal flash attention (fp32)
    attn_kernel<<<dim3(SEQ / 64, NHEADS, 4), 256, 224000>>>(qkv, attn);

    // 4) Output projection (bf16x3 via mma.sync)
    {
        long tA = (long)T_TOK * HIDD;
        long tB = (long)HIDD * HIDD;
        pack_split_kernel<<<(unsigned)((tA + 255) / 256), 256>>>(attn, pA, 0, tA);
        pack_split_kernel<<<(unsigned)((tB + 255) / 256), 256>>>(wo,   pB, 1, tB);
        gemm_mma_kernel<<<dim3(HIDD / 128, T_TOK / 128), 256, gemm_smem>>>(pA, pB, out, HIDD);
    }
}